// round 1
// baseline (speedup 1.0000x reference)
#include <cuda_runtime.h>
#include <cstdint>
#include <math.h>

// ============================================================================
// ProbSparse attention: B=4,H=8,T=12,N=325,D=64, FACTOR=5 -> U=30
// out[b,n,t,h*64+d] = ctx[b,h,t,n,d]
// ============================================================================

#define Bc 4
#define Hc 8
#define Tc 12
#define Nc 325
#define Dc 64
#define Uc 30
#define Gc (Bc*Hc*Tc)      // 384 groups
#define NT 384             // threads per block (12 warps)
#define NW 12
#define KVS 68             // padded row stride (floats) for K/V tiles
#define SCS 328            // scores row stride

// JAX threefry mode: 1 = partitionable (default in JAX >= 0.5), 0 = original
#define JAX_PARTITIONABLE 1

// ---------------- shared memory layout (float offsets) ----------------
#define OFF_KV   0                       // 325*68 = 22100
#define OFF_M    (Nc*KVS)                // 22100 .. +328
#define OFF_S    (OFF_M + 332)           // 22432 : scores 30*328 = 9840
#define OFF_Q    (OFF_S + Uc*SCS)        // 32272 : 30*64
#define OFF_UPD  (OFF_Q + Uc*Dc)         // 34192 : 30*64
#define OFF_MEAN (OFF_UPD + Uc*Dc)       // 36112 : 64
#define OFF_RED  (OFF_MEAN + 64)         // 36176 : 512 floats
#define OFF_REDI (OFF_RED + 512)         // 36688 : 512 ints
#define OFF_SEL  (OFF_REDI + 512)        // 37200 : 32 ints
#define OFF_RANK (OFF_SEL + 32)          // 37232 : 325 ints
#define SMEM_FLOATS (OFF_RANK + Nc + 3)  // 37560
#define SMEM_BYTES (SMEM_FLOATS * 4)     // 150240 B

__device__ int g_idx[Nc * Uc];

// ---------------- threefry2x32 (exact JAX schedule) ----------------
__device__ __forceinline__ uint32_t rotl32(uint32_t x, int r) {
    return (x << r) | (x >> (32 - r));
}

__device__ __forceinline__ void tf2x32(uint32_t k0, uint32_t k1,
                                       uint32_t x0, uint32_t x1,
                                       uint32_t& o0, uint32_t& o1) {
    uint32_t ks2 = k0 ^ k1 ^ 0x1BD11BDAu;
    x0 += k0; x1 += k1;
#define TF_R(r) { x0 += x1; x1 = rotl32(x1, r); x1 ^= x0; }
    TF_R(13) TF_R(15) TF_R(26) TF_R(6)   x0 += k1;  x1 += ks2 + 1u;
    TF_R(17) TF_R(29) TF_R(16) TF_R(24)  x0 += ks2; x1 += k0  + 2u;
    TF_R(13) TF_R(15) TF_R(26) TF_R(6)   x0 += k0;  x1 += k1  + 3u;
    TF_R(17) TF_R(29) TF_R(16) TF_R(24)  x0 += k1;  x1 += ks2 + 4u;
    TF_R(13) TF_R(15) TF_R(26) TF_R(6)   x0 += ks2; x1 += k0  + 5u;
#undef TF_R
    o0 = x0; o1 = x1;
}

// idx_sample[n,u] = jax.random.randint(key(42), (325,30), 0, 325), flat j = n*30+u
__global__ void idx_kernel() {
    int j = blockIdx.x * blockDim.x + threadIdx.x;
    if (j >= Nc * Uc) return;

    const uint32_t SPAN = 325u;
    const uint32_t MULT = 321u;  // (2^32) mod 325
    uint32_t hi, lo;

#if JAX_PARTITIONABLE
    // split: k_i = threefry(key, (0, i)); bits: xor of pair over 64-bit iota
    uint32_t a0, a1, b0, b1;
    tf2x32(0u, 42u, 0u, 0u, a0, a1);   // k1
    tf2x32(0u, 42u, 0u, 1u, b0, b1);   // k2
    uint32_t h0, h1, l0, l1;
    tf2x32(a0, a1, 0u, (uint32_t)j, h0, h1);
    hi = h0 ^ h1;
    tf2x32(b0, b1, 0u, (uint32_t)j, l0, l1);
    lo = l0 ^ l1;
#else
    // original (non-partitionable) scheme
    uint32_t A0, A1, B0, B1;
    tf2x32(0u, 42u, 0u, 2u, A0, A1);   // pair (0,2)
    tf2x32(0u, 42u, 1u, 3u, B0, B1);   // pair (1,3)
    uint32_t k1a = A0, k1b = B0;       // k1 = (f(0,2).x, f(1,3).x)
    uint32_t k2a = A1, k2b = B1;       // k2 = (f(0,2).y, f(1,3).y)
    const int HALF = (Nc * Uc) / 2;    // 4875 (even total)
    uint32_t p0, p1;
    if (j < HALF) {
        tf2x32(k1a, k1b, (uint32_t)j, (uint32_t)(j + HALF), p0, p1);
        hi = p0;
        tf2x32(k2a, k2b, (uint32_t)j, (uint32_t)(j + HALF), p0, p1);
        lo = p0;
    } else {
        tf2x32(k1a, k1b, (uint32_t)(j - HALF), (uint32_t)j, p0, p1);
        hi = p1;
        tf2x32(k2a, k2b, (uint32_t)(j - HALF), (uint32_t)j, p0, p1);
        lo = p1;
    }
#endif
    uint32_t v = ((hi % SPAN) * MULT + (lo % SPAN)) % SPAN;
    g_idx[j] = (int)v;
}

// ---------------- main fused kernel: one block per (b,h,t) group ----------------
__global__ __launch_bounds__(NT, 1)
void probsparse_kernel(const float* __restrict__ Q,
                       const float* __restrict__ K,
                       const float* __restrict__ V,
                       float* __restrict__ out) {
    extern __shared__ float sm[];
    float* sKV   = sm + OFF_KV;
    float* sM    = sm + OFF_M;
    float* sS    = sm + OFF_S;
    float* sQ    = sm + OFF_Q;
    float* sUpd  = sm + OFF_UPD;
    float* sMean = sm + OFF_MEAN;
    float* sRed  = sm + OFF_RED;
    int*   sRedI = (int*)(sm + OFF_REDI);
    int*   sSel  = (int*)(sm + OFF_SEL);
    int*   sRank = (int*)(sm + OFF_RANK);

    const int g    = blockIdx.x;
    const int tid  = threadIdx.x;
    const int lane = tid & 31;
    const int warp = tid >> 5;
    const size_t base = (size_t)g * Nc * Dc;

    // ---- phase 1: load keys into padded SMEM; init rank ----
    {
        const float4* K4 = (const float4*)(K + base);
        for (int i = tid; i < Nc * Dc / 4; i += NT) {
            int n = i >> 4, d4 = i & 15;
            *(float4*)&sKV[n * KVS + d4 * 4] = K4[i];
        }
        for (int i = tid; i < Nc; i += NT) sRank[i] = -1;
    }
    __syncthreads();

    // ---- phase 2: sparsity measure M[n] = max_u(qk) - mean_u(qk) ----
    if (tid < Nc) {
        float4 q4[16];
        const float4* Qr = (const float4*)(Q + base + (size_t)tid * Dc);
#pragma unroll
        for (int j = 0; j < 16; j++) q4[j] = Qr[j];
        float mx = -INFINITY, sum = 0.f;
        const int* idxp = g_idx + tid * Uc;
#pragma unroll 2
        for (int u = 0; u < Uc; u++) {
            int kn = idxp[u];
            const float4* kr = (const float4*)&sKV[kn * KVS];
            float acc = 0.f;
#pragma unroll
            for (int j = 0; j < 16; j++) {
                float4 kv = kr[j];
                acc += q4[j].x * kv.x + q4[j].y * kv.y
                     + q4[j].z * kv.z + q4[j].w * kv.w;
            }
            mx = fmaxf(mx, acc);
            sum += acc;
        }
        sM[tid] = mx - sum * (1.0f / Uc);
    }
    __syncthreads();

    // ---- phase 3: top-30 by iterative argmax (ties -> lowest index) ----
    for (int it = 0; it < Uc; it++) {
        float v = (tid < Nc) ? sM[tid] : -INFINITY;
        sRed[tid]  = v;
        sRedI[tid] = tid;
        if (tid < 512 - NT) { sRed[tid + NT] = -INFINITY; sRedI[tid + NT] = 0x7fffffff; }
        __syncthreads();
        for (int s = 256; s > 0; s >>= 1) {
            if (tid < s) {
                float a = sRed[tid], bv = sRed[tid + s];
                int ai = sRedI[tid], bi = sRedI[tid + s];
                if (bv > a || (bv == a && bi < ai)) { sRed[tid] = bv; sRedI[tid] = bi; }
            }
            __syncthreads();
        }
        if (tid == 0) {
            int win = sRedI[0];
            sSel[it]   = win;
            sRank[win] = it;
            sM[win]    = -INFINITY;
        }
        __syncthreads();
    }

    // ---- phase 4: gather selected queries ----
    for (int i = tid; i < Uc * Dc; i += NT) {
        int u = i >> 6, d = i & 63;
        sQ[u * Dc + d] = Q[base + (size_t)sSel[u] * Dc + d];
    }
    __syncthreads();

    // ---- phase 5: scores + softmax (warp per selected query) ----
    for (int u = warp; u < Uc; u += NW) {
        const float4* q4 = (const float4*)&sQ[u * Dc];
        float lmax = -INFINITY;
        for (int n = lane; n < Nc; n += 32) {
            const float4* kr = (const float4*)&sKV[n * KVS];
            float acc = 0.f;
#pragma unroll
            for (int j = 0; j < 16; j++) {
                float4 a = q4[j], b = kr[j];
                acc += a.x * b.x + a.y * b.y + a.z * b.z + a.w * b.w;
            }
            acc *= 0.125f;  // 1/sqrt(64)
            sS[u * SCS + n] = acc;
            lmax = fmaxf(lmax, acc);
        }
#pragma unroll
        for (int o = 16; o > 0; o >>= 1)
            lmax = fmaxf(lmax, __shfl_xor_sync(0xffffffffu, lmax, o));
        float lsum = 0.f;
        for (int n = lane; n < Nc; n += 32) {
            float e = expf(sS[u * SCS + n] - lmax);
            sS[u * SCS + n] = e;
            lsum += e;
        }
#pragma unroll
        for (int o = 16; o > 0; o >>= 1)
            lsum += __shfl_xor_sync(0xffffffffu, lsum, o);
        float inv = 1.0f / lsum;
        for (int n = lane; n < Nc; n += 32) sS[u * SCS + n] *= inv;
    }
    __syncthreads();

    // ---- phase 6: overwrite key tile with values ----
    {
        const float4* V4 = (const float4*)(V + base);
        for (int i = tid; i < Nc * Dc / 4; i += NT) {
            int n = i >> 4, d4 = i & 15;
            *(float4*)&sKV[n * KVS + d4 * 4] = V4[i];
        }
    }
    __syncthreads();

    // ---- phase 7: column mean of values ----
    if (tid < Dc) {
        float s = 0.f;
        for (int n = 0; n < Nc; n++) s += sKV[n * KVS + tid];
        sMean[tid] = s * (1.0f / Nc);
    }

    // ---- phase 8: upd[u,:] = probs[u,:] @ V (warp per u, lanes over d) ----
    for (int u = warp; u < Uc; u += NW) {
        float a0 = 0.f, a1 = 0.f;
        const float* ps = &sS[u * SCS];
#pragma unroll 4
        for (int n = 0; n < Nc; n++) {
            float p = ps[n];
            a0 += p * sKV[n * KVS + lane];
            a1 += p * sKV[n * KVS + lane + 32];
        }
        sUpd[u * Dc + lane]      = a0;
        sUpd[u * Dc + lane + 32] = a1;
    }
    __syncthreads();

    // ---- phase 9: write output (selected -> attention, else column mean) ----
    {
        const int b = g / (Hc * Tc);
        const int h = (g / Tc) % Hc;
        const int t = g % Tc;
        for (int i = tid; i < Nc * Dc / 4; i += NT) {
            int n = i >> 4, d4 = (i & 15) * 4;
            int r = sRank[n];
            float4 v = (r >= 0) ? *(float4*)&sUpd[r * Dc + d4]
                                : *(float4*)&sMean[d4];
            size_t o = ((size_t)(b * Nc + n) * Tc + t) * (size_t)(Hc * Dc)
                     + h * Dc + d4;
            *(float4*)&out[o] = v;
        }
    }
}

// ---------------- launch ----------------
extern "C" void kernel_launch(void* const* d_in, const int* in_sizes, int n_in,
                              void* d_out, int out_size) {
    const float* Q = (const float*)d_in[0];
    const float* K = (const float*)d_in[1];
    const float* V = (const float*)d_in[2];
    float* out = (float*)d_out;

    cudaFuncSetAttribute(probsparse_kernel,
                         cudaFuncAttributeMaxDynamicSharedMemorySize, SMEM_BYTES);

    idx_kernel<<<(Nc * Uc + 255) / 256, 256>>>();
    probsparse_kernel<<<Gc, NT, SMEM_BYTES>>>(Q, K, V, out);
}

// round 2
// speedup vs baseline: 1.4598x; 1.4598x over previous
#include <cuda_runtime.h>
#include <cstdint>
#include <math.h>

// ============================================================================
// ProbSparse attention: B=4,H=8,T=12,N=325,D=64, FACTOR=5 -> U=30
// out[b,n,t,h*64+d] = ctx[b,h,t,n,d]
// ============================================================================

#define Bc 4
#define Hc 8
#define Tc 12
#define Nc 325
#define Dc 64
#define Uc 30
#define Gc (Bc*Hc*Tc)      // 384 groups
#define NT 480             // threads per block (15 warps)
#define NW 15
#define KVS 68             // padded row stride (floats) for K/V tiles
#define SCS 328            // scores row stride

// ---------------- shared memory layout (float offsets) ----------------
#define OFF_KV   0                       // 325*68 = 22100
#define OFF_M    (Nc*KVS)                // 22100 .. +328
#define OFF_S    (OFF_M + 332)           // scores 30*328
#define OFF_Q    (OFF_S + Uc*SCS)        // 30*64
#define OFF_UPD  (OFF_Q + Uc*Dc)         // 30*64
#define OFF_MEAN (OFF_UPD + Uc*Dc)       // 64
#define OFF_RED  (OFF_MEAN + 64)         // 512 floats (partial means)
#define OFF_SEL  (OFF_RED + 512)         // 32 ints
#define OFF_RANK (OFF_SEL + 32)          // 325 ints
#define SMEM_FLOATS (OFF_RANK + Nc + 3)
#define SMEM_BYTES (SMEM_FLOATS * 4)     // ~148KB

__device__ int g_idx[Nc * Uc];

// ---------------- threefry2x32 (exact JAX schedule) ----------------
__device__ __forceinline__ uint32_t rotl32(uint32_t x, int r) {
    return (x << r) | (x >> (32 - r));
}

__device__ __forceinline__ void tf2x32(uint32_t k0, uint32_t k1,
                                       uint32_t x0, uint32_t x1,
                                       uint32_t& o0, uint32_t& o1) {
    uint32_t ks2 = k0 ^ k1 ^ 0x1BD11BDAu;
    x0 += k0; x1 += k1;
#define TF_R(r) { x0 += x1; x1 = rotl32(x1, r); x1 ^= x0; }
    TF_R(13) TF_R(15) TF_R(26) TF_R(6)   x0 += k1;  x1 += ks2 + 1u;
    TF_R(17) TF_R(29) TF_R(16) TF_R(24)  x0 += ks2; x1 += k0  + 2u;
    TF_R(13) TF_R(15) TF_R(26) TF_R(6)   x0 += k0;  x1 += k1  + 3u;
    TF_R(17) TF_R(29) TF_R(16) TF_R(24)  x0 += k1;  x1 += ks2 + 4u;
    TF_R(13) TF_R(15) TF_R(26) TF_R(6)   x0 += ks2; x1 += k0  + 5u;
#undef TF_R
    o0 = x0; o1 = x1;
}

// idx_sample[n,u] = jax.random.randint(key(42), (325,30), 0, 325), flat j = n*30+u
// (JAX partitionable threefry — verified bit-exact in round 1)
__global__ void idx_kernel() {
    int j = blockIdx.x * blockDim.x + threadIdx.x;
    if (j >= Nc * Uc) return;

    const uint32_t SPAN = 325u;
    const uint32_t MULT = 321u;  // (2^32) mod 325
    uint32_t a0, a1, b0, b1;
    tf2x32(0u, 42u, 0u, 0u, a0, a1);   // subkey 1
    tf2x32(0u, 42u, 0u, 1u, b0, b1);   // subkey 2
    uint32_t h0, h1, l0, l1;
    tf2x32(a0, a1, 0u, (uint32_t)j, h0, h1);
    uint32_t hi = h0 ^ h1;
    tf2x32(b0, b1, 0u, (uint32_t)j, l0, l1);
    uint32_t lo = l0 ^ l1;
    uint32_t v = ((hi % SPAN) * MULT + (lo % SPAN)) % SPAN;
    g_idx[j] = (int)v;
}

__device__ __forceinline__ float dot4(float4 a, float4 b) {
    return a.x * b.x + a.y * b.y + a.z * b.z + a.w * b.w;
}

// ---------------- main fused kernel: one block per (b,h,t) group ----------------
__global__ __launch_bounds__(NT, 1)
void probsparse_kernel(const float* __restrict__ Q,
                       const float* __restrict__ K,
                       const float* __restrict__ V,
                       float* __restrict__ out) {
    extern __shared__ float sm[];
    float* sKV   = sm + OFF_KV;
    float* sM    = sm + OFF_M;
    float* sS    = sm + OFF_S;
    float* sQ    = sm + OFF_Q;
    float* sUpd  = sm + OFF_UPD;
    float* sMean = sm + OFF_MEAN;
    float* sRed  = sm + OFF_RED;
    int*   sSel  = (int*)(sm + OFF_SEL);
    int*   sRank = (int*)(sm + OFF_RANK);

    const int g    = blockIdx.x;
    const int tid  = threadIdx.x;
    const int lane = tid & 31;
    const int warp = tid >> 5;
    const size_t base = (size_t)g * Nc * Dc;

    // ---- phase 1: load keys into padded SMEM; init rank ----
    {
        const float4* K4 = (const float4*)(K + base);
        for (int i = tid; i < Nc * Dc / 4; i += NT) {
            int n = i >> 4, d4 = i & 15;
            *(float4*)&sKV[n * KVS + d4 * 4] = K4[i];
        }
        for (int i = tid; i < Nc; i += NT) sRank[i] = -1;
    }
    __syncthreads();

    // ---- phase 2: sparsity measure M[n] = max_u(qk) - mean_u(qk) ----
    if (tid < Nc) {
        float4 q4[16];
        const float4* Qr = (const float4*)(Q + base + (size_t)tid * Dc);
#pragma unroll
        for (int j = 0; j < 16; j++) q4[j] = Qr[j];
        float mx = -INFINITY, sum = 0.f;
        const int* idxp = g_idx + tid * Uc;
#pragma unroll 2
        for (int u = 0; u < Uc; u += 2) {
            int kn0 = idxp[u], kn1 = idxp[u + 1];
            const float4* kr0 = (const float4*)&sKV[kn0 * KVS];
            const float4* kr1 = (const float4*)&sKV[kn1 * KVS];
            float a0 = 0.f, a1 = 0.f, a2 = 0.f, a3 = 0.f;
            float b0 = 0.f, b1 = 0.f, b2 = 0.f, b3 = 0.f;
#pragma unroll
            for (int j = 0; j < 16; j += 4) {
                a0 += dot4(q4[j],     kr0[j]);
                a1 += dot4(q4[j + 1], kr0[j + 1]);
                a2 += dot4(q4[j + 2], kr0[j + 2]);
                a3 += dot4(q4[j + 3], kr0[j + 3]);
                b0 += dot4(q4[j],     kr1[j]);
                b1 += dot4(q4[j + 1], kr1[j + 1]);
                b2 += dot4(q4[j + 2], kr1[j + 2]);
                b3 += dot4(q4[j + 3], kr1[j + 3]);
            }
            float accA = (a0 + a1) + (a2 + a3);
            float accB = (b0 + b1) + (b2 + b3);
            mx = fmaxf(mx, fmaxf(accA, accB));
            sum += accA + accB;
        }
        sM[tid] = mx - sum * (1.0f / Uc);
    }
    __syncthreads();

    // ---- phase 3: top-30 via parallel rank counting (ties -> lowest index) ----
    if (tid < Nc) {
        float mi = sM[tid];
        int rank = 0;
        for (int j = 0; j < Nc; j++) {
            float mj = sM[j];   // broadcast read
            rank += (mj > mi) || (mj == mi && j < tid) ? 1 : 0;
        }
        if (rank < Uc) { sRank[tid] = rank; sSel[rank] = tid; }
    }
    __syncthreads();

    // ---- phase 4: gather selected queries ----
    for (int i = tid; i < Uc * Dc; i += NT) {
        int u = i >> 6, d = i & 63;
        sQ[u * Dc + d] = Q[base + (size_t)sSel[u] * Dc + d];
    }
    __syncthreads();

    // ---- phase 5: scores + softmax (warp per selected query, 2 rounds) ----
    for (int u = warp; u < Uc; u += NW) {
        const float4* q4 = (const float4*)&sQ[u * Dc];
        float lmax = -INFINITY;
        for (int n = lane; n < Nc; n += 32) {
            const float4* kr = (const float4*)&sKV[n * KVS];
            float a0 = 0.f, a1 = 0.f, a2 = 0.f, a3 = 0.f;
#pragma unroll
            for (int j = 0; j < 16; j += 4) {
                a0 += dot4(q4[j],     kr[j]);
                a1 += dot4(q4[j + 1], kr[j + 1]);
                a2 += dot4(q4[j + 2], kr[j + 2]);
                a3 += dot4(q4[j + 3], kr[j + 3]);
            }
            float acc = ((a0 + a1) + (a2 + a3)) * 0.125f;  // 1/sqrt(64)
            sS[u * SCS + n] = acc;
            lmax = fmaxf(lmax, acc);
        }
#pragma unroll
        for (int o = 16; o > 0; o >>= 1)
            lmax = fmaxf(lmax, __shfl_xor_sync(0xffffffffu, lmax, o));
        float lsum = 0.f;
        for (int n = lane; n < Nc; n += 32) {
            float e = __expf(sS[u * SCS + n] - lmax);
            sS[u * SCS + n] = e;
            lsum += e;
        }
#pragma unroll
        for (int o = 16; o > 0; o >>= 1)
            lsum += __shfl_xor_sync(0xffffffffu, lsum, o);
        float inv = 1.0f / lsum;
        for (int n = lane; n < Nc; n += 32) sS[u * SCS + n] *= inv;
    }
    __syncthreads();

    // ---- phase 6: overwrite key tile with values ----
    {
        const float4* V4 = (const float4*)(V + base);
        for (int i = tid; i < Nc * Dc / 4; i += NT) {
            int n = i >> 4, d4 = i & 15;
            *(float4*)&sKV[n * KVS + d4 * 4] = V4[i];
        }
    }
    __syncthreads();

    // ---- phase 7: column mean of values (parallel over 6 row-slices) ----
    if (tid < 384) {
        int d = tid & 63, s = tid >> 6;            // 6 slices of <=55 rows
        int n0 = s * 55, n1 = min(Nc, n0 + 55);
        float acc = 0.f;
        for (int n = n0; n < n1; n++) acc += sKV[n * KVS + d];
        sRed[s * 64 + d] = acc;
    }
    __syncthreads();
    if (tid < Dc) {
        float s = 0.f;
#pragma unroll
        for (int k = 0; k < 6; k++) s += sRed[k * 64 + tid];
        sMean[tid] = s * (1.0f / Nc);
    }

    // ---- phase 8: upd[u,:] = probs[u,:] @ V (warp per u, lanes over d) ----
    for (int u = warp; u < Uc; u += NW) {
        float a00 = 0.f, a01 = 0.f, a10 = 0.f, a11 = 0.f;
        const float* ps = &sS[u * SCS];
        int n = 0;
        for (; n + 1 < Nc; n += 2) {
            float p0 = ps[n], p1 = ps[n + 1];
            a00 += p0 * sKV[n * KVS + lane];
            a01 += p0 * sKV[n * KVS + lane + 32];
            a10 += p1 * sKV[(n + 1) * KVS + lane];
            a11 += p1 * sKV[(n + 1) * KVS + lane + 32];
        }
        {   // tail (n = 324)
            float p0 = ps[n];
            a00 += p0 * sKV[n * KVS + lane];
            a01 += p0 * sKV[n * KVS + lane + 32];
        }
        sUpd[u * Dc + lane]      = a00 + a10;
        sUpd[u * Dc + lane + 32] = a01 + a11;
    }
    __syncthreads();

    // ---- phase 9: write output (selected -> attention, else column mean) ----
    {
        const int b = g / (Hc * Tc);
        const int h = (g / Tc) % Hc;
        const int t = g % Tc;
        for (int i = tid; i < Nc * Dc / 4; i += NT) {
            int n = i >> 4, d4 = (i & 15) * 4;
            int r = sRank[n];
            float4 v = (r >= 0) ? *(float4*)&sUpd[r * Dc + d4]
                                : *(float4*)&sMean[d4];
            size_t o = ((size_t)(b * Nc + n) * Tc + t) * (size_t)(Hc * Dc)
                     + h * Dc + d4;
            *(float4*)&out[o] = v;
        }
    }
}

// ---------------- launch ----------------
extern "C" void kernel_launch(void* const* d_in, const int* in_sizes, int n_in,
                              void* d_out, int out_size) {
    const float* Q = (const float*)d_in[0];
    const float* K = (const float*)d_in[1];
    const float* V = (const float*)d_in[2];
    float* out = (float*)d_out;

    cudaFuncSetAttribute(probsparse_kernel,
                         cudaFuncAttributeMaxDynamicSharedMemorySize, SMEM_BYTES);

    idx_kernel<<<(Nc * Uc + 255) / 256, 256>>>();
    probsparse_kernel<<<Gc, NT, SMEM_BYTES>>>(Q, K, V, out);
}

// round 3
// speedup vs baseline: 1.7889x; 1.2255x over previous
#include <cuda_runtime.h>
#include <cstdint>
#include <math.h>

// ============================================================================
// ProbSparse attention: B=4,H=8,T=12,N=325,D=64, FACTOR=5 -> U=30
// out[b,n,t,h*64+d] = ctx[b,h,t,n,d]
// ============================================================================

#define Bc 4
#define Hc 8
#define Tc 12
#define Nc 325
#define Dc 64
#define Uc 30
#define Gc (Bc*Hc*Tc)      // 384 groups
#define NT 480             // threads per block (15 warps)
#define NW 15
#define KVS 68             // padded row stride (floats) for K/V tiles
#define SCS 328            // e-values row stride
#define NSTEP 11           // ceil(325/32)

// ---------------- shared memory layout (float offsets) ----------------
#define OFF_KV   0                       // 325*68 = 22100
#define OFF_M    (Nc*KVS)                // +328
#define OFF_S    (OFF_M + 332)           // e-values 30*328
#define OFF_Q    (OFF_S + Uc*SCS)        // 30*64
#define OFF_UPD  (OFF_Q + Uc*Dc)         // 30*64
#define OFF_MEAN (OFF_UPD + Uc*Dc)       // 64
#define OFF_RED  (OFF_MEAN + 64)         // 512 floats (partial means)
#define OFF_SEL  (OFF_RED + 512)         // 32 ints
#define OFF_RANK (OFF_SEL + 32)          // 325 ints
#define SMEM_FLOATS (OFF_RANK + Nc + 3)
#define SMEM_BYTES (SMEM_FLOATS * 4)     // ~148KB

__device__ int g_idx[Nc * Uc];

// ---------------- threefry2x32 (exact JAX schedule) ----------------
__device__ __forceinline__ uint32_t rotl32(uint32_t x, int r) {
    return (x << r) | (x >> (32 - r));
}

__device__ __forceinline__ void tf2x32(uint32_t k0, uint32_t k1,
                                       uint32_t x0, uint32_t x1,
                                       uint32_t& o0, uint32_t& o1) {
    uint32_t ks2 = k0 ^ k1 ^ 0x1BD11BDAu;
    x0 += k0; x1 += k1;
#define TF_R(r) { x0 += x1; x1 = rotl32(x1, r); x1 ^= x0; }
    TF_R(13) TF_R(15) TF_R(26) TF_R(6)   x0 += k1;  x1 += ks2 + 1u;
    TF_R(17) TF_R(29) TF_R(16) TF_R(24)  x0 += ks2; x1 += k0  + 2u;
    TF_R(13) TF_R(15) TF_R(26) TF_R(6)   x0 += k0;  x1 += k1  + 3u;
    TF_R(17) TF_R(29) TF_R(16) TF_R(24)  x0 += k1;  x1 += ks2 + 4u;
    TF_R(13) TF_R(15) TF_R(26) TF_R(6)   x0 += ks2; x1 += k0  + 5u;
#undef TF_R
    o0 = x0; o1 = x1;
}

// idx_sample = jax.random.randint(key(42), (325,30), 0, 325)  [verified bit-exact]
__global__ void idx_kernel() {
    int j = blockIdx.x * blockDim.x + threadIdx.x;
    if (j >= Nc * Uc) return;
    const uint32_t SPAN = 325u;
    const uint32_t MULT = 321u;  // (2^32) mod 325
    uint32_t a0, a1, b0, b1;
    tf2x32(0u, 42u, 0u, 0u, a0, a1);
    tf2x32(0u, 42u, 0u, 1u, b0, b1);
    uint32_t h0, h1, l0, l1;
    tf2x32(a0, a1, 0u, (uint32_t)j, h0, h1);
    uint32_t hi = h0 ^ h1;
    tf2x32(b0, b1, 0u, (uint32_t)j, l0, l1);
    uint32_t lo = l0 ^ l1;
    g_idx[j] = (int)(((hi % SPAN) * MULT + (lo % SPAN)) % SPAN);
}

__device__ __forceinline__ float dot4(float4 a, float4 b) {
    return a.x * b.x + a.y * b.y + a.z * b.z + a.w * b.w;
}

// ---------------- main fused kernel: one block per (b,h,t) group ----------------
__global__ __launch_bounds__(NT, 1)
void probsparse_kernel(const float* __restrict__ Q,
                       const float* __restrict__ K,
                       const float* __restrict__ V,
                       float* __restrict__ out) {
    extern __shared__ float sm[];
    float* sKV   = sm + OFF_KV;
    float* sM    = sm + OFF_M;
    float* sS    = sm + OFF_S;
    float* sQ    = sm + OFF_Q;
    float* sUpd  = sm + OFF_UPD;
    float* sMean = sm + OFF_MEAN;
    float* sRed  = sm + OFF_RED;
    int*   sSel  = (int*)(sm + OFF_SEL);
    int*   sRank = (int*)(sm + OFF_RANK);

    const int g    = blockIdx.x;
    const int tid  = threadIdx.x;
    const int lane = tid & 31;
    const int warp = tid >> 5;
    const size_t base = (size_t)g * Nc * Dc;

    // ---- phase 1: load keys into padded SMEM; init rank ----
    {
        const float4* K4 = (const float4*)(K + base);
        for (int i = tid; i < Nc * Dc / 4; i += NT) {
            int n = i >> 4, d4 = i & 15;
            *(float4*)&sKV[n * KVS + d4 * 4] = K4[i];
        }
        for (int i = tid; i < Nc; i += NT) sRank[i] = -1;
    }
    __syncthreads();

    // ---- phase 2: sparsity measure M[n] = max_u(qk) - mean_u(qk) ----
    if (tid < Nc) {
        float4 q4[16];
        const float4* Qr = (const float4*)(Q + base + (size_t)tid * Dc);
#pragma unroll
        for (int j = 0; j < 16; j++) q4[j] = Qr[j];
        float mx = -INFINITY, sum = 0.f;
        const int* idxp = g_idx + tid * Uc;
#pragma unroll 2
        for (int u = 0; u < Uc; u += 2) {
            int kn0 = idxp[u], kn1 = idxp[u + 1];
            const float4* kr0 = (const float4*)&sKV[kn0 * KVS];
            const float4* kr1 = (const float4*)&sKV[kn1 * KVS];
            float a0 = 0.f, a1 = 0.f, a2 = 0.f, a3 = 0.f;
            float b0 = 0.f, b1 = 0.f, b2 = 0.f, b3 = 0.f;
#pragma unroll
            for (int j = 0; j < 16; j += 4) {
                a0 += dot4(q4[j],     kr0[j]);
                a1 += dot4(q4[j + 1], kr0[j + 1]);
                a2 += dot4(q4[j + 2], kr0[j + 2]);
                a3 += dot4(q4[j + 3], kr0[j + 3]);
                b0 += dot4(q4[j],     kr1[j]);
                b1 += dot4(q4[j + 1], kr1[j + 1]);
                b2 += dot4(q4[j + 2], kr1[j + 2]);
                b3 += dot4(q4[j + 3], kr1[j + 3]);
            }
            float accA = (a0 + a1) + (a2 + a3);
            float accB = (b0 + b1) + (b2 + b3);
            mx = fmaxf(mx, fmaxf(accA, accB));
            sum += accA + accB;
        }
        sM[tid] = mx - sum * (1.0f / Uc);
    }
    __syncthreads();

    // ---- phase 3: top-30 via parallel rank counting (ties -> lowest index) ----
    if (tid < Nc) {
        float mi = sM[tid];
        int rank = 0;
        for (int j = 0; j < Nc; j++) {
            float mj = sM[j];   // broadcast read
            rank += (mj > mi) || (mj == mi && j < tid) ? 1 : 0;
        }
        if (rank < Uc) { sRank[tid] = rank; sSel[rank] = tid; }
    }
    __syncthreads();

    // ---- phase 4: gather selected queries ----
    for (int i = tid; i < Uc * Dc; i += NT) {
        int u = i >> 6, d = i & 63;
        sQ[u * Dc + d] = Q[base + (size_t)sSel[u] * Dc + d];
    }
    __syncthreads();

    // ========================================================================
    // phase 5: scores + softmax. Warp w owns u0=w, u1=w+15.
    // Lane pairs (l, l+16) split the 64-d dot: lane<16 does d[0:32),
    // lane>=16 does d[32:64); combined with shfl_xor(16). Each K row is read
    // once per warp serving BOTH queries.
    // ========================================================================
    const int u0 = warp, u1 = warp + NW;
    const int half = lane >> 4;         // 0 or 1
    const int lsub = lane & 15;
    const int d0 = half << 5;           // 0 or 32
    float inv0, inv1;                   // kept live into phase 8
    {
        float4 qa[8], qb[8];
        const float4* qa4 = (const float4*)&sQ[u0 * Dc + d0];
        const float4* qb4 = (const float4*)&sQ[u1 * Dc + d0];
#pragma unroll
        for (int j = 0; j < 8; j++) { qa[j] = qa4[j]; qb[j] = qb4[j]; }

        float sreg0[NSTEP], sreg1[NSTEP];
        float lmax0 = -INFINITY, lmax1 = -INFINITY;
#pragma unroll
        for (int t = 0; t < NSTEP; t++) {
            int bn  = t * 32;
            int nlo = bn + lsub;        // row for partials (lanes paired)
            int nhi = bn + 16 + lsub;
            int alo = min(nlo, Nc - 1) * KVS + d0;
            int ahi = min(nhi, Nc - 1) * KVS + d0;
            const float4* klo = (const float4*)&sKV[alo];
            const float4* khi = (const float4*)&sKV[ahi];
            float p00 = 0.f, p01 = 0.f, p10 = 0.f, p11 = 0.f;
#pragma unroll
            for (int j = 0; j < 8; j++) {
                float4 kl = klo[j], kh = khi[j];
                p00 += dot4(qa[j], kl);
                p01 += dot4(qb[j], kl);
                p10 += dot4(qa[j], kh);
                p11 += dot4(qb[j], kh);
            }
            // combine d-halves across lane pairs
            p00 += __shfl_xor_sync(0xffffffffu, p00, 16);
            p01 += __shfl_xor_sync(0xffffffffu, p01, 16);
            p10 += __shfl_xor_sync(0xffffffffu, p10, 16);
            p11 += __shfl_xor_sync(0xffffffffu, p11, 16);
            // lane stores n = bn + lane: lane<16 -> nlo, lane>=16 -> nhi
            int n = bn + lane;
            float s0 = (half ? p10 : p00) * 0.125f;
            float s1 = (half ? p11 : p01) * 0.125f;
            bool ok = (n < Nc);
            sreg0[t] = s0; sreg1[t] = s1;
            lmax0 = fmaxf(lmax0, ok ? s0 : -INFINITY);
            lmax1 = fmaxf(lmax1, ok ? s1 : -INFINITY);
        }
#pragma unroll
        for (int o = 16; o > 0; o >>= 1) {
            lmax0 = fmaxf(lmax0, __shfl_xor_sync(0xffffffffu, lmax0, o));
            lmax1 = fmaxf(lmax1, __shfl_xor_sync(0xffffffffu, lmax1, o));
        }
        float lsum0 = 0.f, lsum1 = 0.f;
#pragma unroll
        for (int t = 0; t < NSTEP; t++) {
            int n = t * 32 + lane;
            if (n < Nc) {
                float e0 = __expf(sreg0[t] - lmax0);
                float e1 = __expf(sreg1[t] - lmax1);
                sS[u0 * SCS + n] = e0;
                sS[u1 * SCS + n] = e1;
                lsum0 += e0; lsum1 += e1;
            }
        }
#pragma unroll
        for (int o = 16; o > 0; o >>= 1) {
            lsum0 += __shfl_xor_sync(0xffffffffu, lsum0, o);
            lsum1 += __shfl_xor_sync(0xffffffffu, lsum1, o);
        }
        inv0 = 1.0f / lsum0;
        inv1 = 1.0f / lsum1;
    }
    __syncthreads();   // all K reads done

    // ---- phase 6: overwrite key tile with values ----
    {
        const float4* V4 = (const float4*)(V + base);
        for (int i = tid; i < Nc * Dc / 4; i += NT) {
            int n = i >> 4, d4 = i & 15;
            *(float4*)&sKV[n * KVS + d4 * 4] = V4[i];
        }
    }
    __syncthreads();

    // ---- phase 7a: partial column sums of values ----
    if (tid < 384) {
        int d = tid & 63, s = tid >> 6;            // 6 slices of <=55 rows
        int n0 = s * 55, n1 = min(Nc, n0 + 55);
        float acc = 0.f;
        for (int n = n0; n < n1; n++) acc += sKV[n * KVS + d];
        sRed[s * 64 + d] = acc;
    }
    __syncthreads();
    // ---- phase 7b: combine mean ----
    if (tid < Dc) {
        float s = 0.f;
#pragma unroll
        for (int k = 0; k < 6; k++) s += sRed[k * 64 + tid];
        sMean[tid] = s * (1.0f / Nc);
    }

    // ========================================================================
    // phase 8: upd = softmax @ V. Same warp->u-pair mapping; each V row read
    // once per warp serves both u's; normalization applied at the end.
    // ========================================================================
    {
        float a00 = 0.f, a01 = 0.f, a10 = 0.f, a11 = 0.f;
        float b00 = 0.f, b01 = 0.f, b10 = 0.f, b11 = 0.f;
        const float* e0p = &sS[u0 * SCS];
        const float* e1p = &sS[u1 * SCS];
        int n = 0;
        for (; n + 1 < Nc; n += 2) {
            float e0a = e0p[n],     e1a = e1p[n];
            float e0b = e0p[n + 1], e1b = e1p[n + 1];
            float v0a = sKV[n * KVS + lane];
            float v1a = sKV[n * KVS + lane + 32];
            float v0b = sKV[(n + 1) * KVS + lane];
            float v1b = sKV[(n + 1) * KVS + lane + 32];
            a00 += e0a * v0a; a01 += e0a * v1a;
            a10 += e1a * v0a; a11 += e1a * v1a;
            b00 += e0b * v0b; b01 += e0b * v1b;
            b10 += e1b * v0b; b11 += e1b * v1b;
        }
        {   // tail n = 324
            float e0a = e0p[n], e1a = e1p[n];
            float v0a = sKV[n * KVS + lane];
            float v1a = sKV[n * KVS + lane + 32];
            a00 += e0a * v0a; a01 += e0a * v1a;
            a10 += e1a * v0a; a11 += e1a * v1a;
        }
        sUpd[u0 * Dc + lane]      = (a00 + b00) * inv0;
        sUpd[u0 * Dc + lane + 32] = (a01 + b01) * inv0;
        sUpd[u1 * Dc + lane]      = (a10 + b10) * inv1;
        sUpd[u1 * Dc + lane + 32] = (a11 + b11) * inv1;
    }
    __syncthreads();

    // ---- phase 9: write output (selected -> attention, else column mean) ----
    {
        const int b = g / (Hc * Tc);
        const int h = (g / Tc) % Hc;
        const int t = g % Tc;
        for (int i = tid; i < Nc * Dc / 4; i += NT) {
            int n = i >> 4, d4 = (i & 15) * 4;
            int r = sRank[n];
            float4 v = (r >= 0) ? *(float4*)&sUpd[r * Dc + d4]
                                : *(float4*)&sMean[d4];
            size_t o = ((size_t)(b * Nc + n) * Tc + t) * (size_t)(Hc * Dc)
                     + h * Dc + d4;
            *(float4*)&out[o] = v;
        }
    }
}

// ---------------- launch ----------------
extern "C" void kernel_launch(void* const* d_in, const int* in_sizes, int n_in,
                              void* d_out, int out_size) {
    const float* Q = (const float*)d_in[0];
    const float* K = (const float*)d_in[1];
    const float* V = (const float*)d_in[2];
    float* out = (float*)d_out;

    cudaFuncSetAttribute(probsparse_kernel,
                         cudaFuncAttributeMaxDynamicSharedMemorySize, SMEM_BYTES);

    idx_kernel<<<(Nc * Uc + 255) / 256, 256>>>();
    probsparse_kernel<<<Gc, NT, SMEM_BYTES>>>(Q, K, V, out);
}

// round 4
// speedup vs baseline: 1.9664x; 1.0992x over previous
#include <cuda_runtime.h>
#include <cstdint>
#include <math.h>

// ============================================================================
// ProbSparse attention: B=4,H=8,T=12,N=325,D=64, FACTOR=5 -> U=30
// out[b,n,t,h*64+d] = ctx[b,h,t,n,d]
// K and V both resident in SMEM; scores/softmax/GEMV fused per warp.
// ============================================================================

#define Bc 4
#define Hc 8
#define Tc 12
#define Nc 325
#define Dc 64
#define Uc 30
#define Gc (Bc*Hc*Tc)      // 384 groups
#define NT 480             // threads per block (15 warps)
#define NW 15
#define KVS 68             // padded row stride (floats)
#define NSTEP 11           // ceil(325/32)

// ---------------- shared memory layout (float offsets) ----------------
#define OFF_K    0                         // 325*68 = 22100
#define OFF_V    (Nc*KVS)                  // 22100 -> 44200
#define OFF_M    (OFF_V + Nc*KVS)          // 328
#define OFF_Q    (OFF_M + 328)             // 30*64
#define OFF_UPD  (OFF_Q + Uc*Dc)           // 30*64
#define OFF_MEAN (OFF_UPD + Uc*Dc)         // 64
#define OFF_RED  (OFF_MEAN + 64)           // 1024 (15 warps x 64 partials)
#define OFF_SEL  (OFF_RED + 1024)          // 32 ints
#define OFF_RANK (OFF_SEL + 32)            // 325 ints (+pad)
#define SMEM_FLOATS (OFF_RANK + Nc + 3)
#define SMEM_BYTES (SMEM_FLOATS * 4)       // ~199.3 KB

__device__ int g_idx[Nc * Uc];

// ---------------- threefry2x32 (exact JAX schedule) ----------------
__device__ __forceinline__ uint32_t rotl32(uint32_t x, int r) {
    return (x << r) | (x >> (32 - r));
}

__device__ __forceinline__ void tf2x32(uint32_t k0, uint32_t k1,
                                       uint32_t x0, uint32_t x1,
                                       uint32_t& o0, uint32_t& o1) {
    uint32_t ks2 = k0 ^ k1 ^ 0x1BD11BDAu;
    x0 += k0; x1 += k1;
#define TF_R(r) { x0 += x1; x1 = rotl32(x1, r); x1 ^= x0; }
    TF_R(13) TF_R(15) TF_R(26) TF_R(6)   x0 += k1;  x1 += ks2 + 1u;
    TF_R(17) TF_R(29) TF_R(16) TF_R(24)  x0 += ks2; x1 += k0  + 2u;
    TF_R(13) TF_R(15) TF_R(26) TF_R(6)   x0 += k0;  x1 += k1  + 3u;
    TF_R(17) TF_R(29) TF_R(16) TF_R(24)  x0 += k1;  x1 += ks2 + 4u;
    TF_R(13) TF_R(15) TF_R(26) TF_R(6)   x0 += ks2; x1 += k0  + 5u;
#undef TF_R
    o0 = x0; o1 = x1;
}

// idx_sample = jax.random.randint(key(42), (325,30), 0, 325)  [verified bit-exact]
__global__ void idx_kernel() {
    int j = blockIdx.x * blockDim.x + threadIdx.x;
    if (j >= Nc * Uc) return;
    const uint32_t SPAN = 325u;
    const uint32_t MULT = 321u;  // (2^32) mod 325
    uint32_t a0, a1, b0, b1;
    tf2x32(0u, 42u, 0u, 0u, a0, a1);
    tf2x32(0u, 42u, 0u, 1u, b0, b1);
    uint32_t h0, h1, l0, l1;
    tf2x32(a0, a1, 0u, (uint32_t)j, h0, h1);
    uint32_t hi = h0 ^ h1;
    tf2x32(b0, b1, 0u, (uint32_t)j, l0, l1);
    uint32_t lo = l0 ^ l1;
    g_idx[j] = (int)(((hi % SPAN) * MULT + (lo % SPAN)) % SPAN);
}

__device__ __forceinline__ float dot4(float4 a, float4 b) {
    return a.x * b.x + a.y * b.y + a.z * b.z + a.w * b.w;
}

__device__ __forceinline__ void cp_async16(uint32_t dst, const void* src) {
    asm volatile("cp.async.cg.shared.global [%0], [%1], 16;\n"
                 :: "r"(dst), "l"(src));
}

// ---------------- main fused kernel: one block per (b,h,t) group ----------------
__global__ __launch_bounds__(NT, 1)
void probsparse_kernel(const float* __restrict__ Q,
                       const float* __restrict__ K,
                       const float* __restrict__ V,
                       float* __restrict__ out) {
    extern __shared__ float sm[];
    float* sK    = sm + OFF_K;
    float* sV    = sm + OFF_V;
    float* sM    = sm + OFF_M;
    float* sQ    = sm + OFF_Q;
    float* sUpd  = sm + OFF_UPD;
    float* sMean = sm + OFF_MEAN;
    float* sRed  = sm + OFF_RED;
    int*   sSel  = (int*)(sm + OFF_SEL);
    int*   sRank = (int*)(sm + OFF_RANK);

    const int g    = blockIdx.x;
    const int tid  = threadIdx.x;
    const int lane = tid & 31;
    const int warp = tid >> 5;
    const size_t base = (size_t)g * Nc * Dc;

    // ---- phase 0: hoist Q row loads (overlap DRAM latency with staging) ----
    float4 q4[16];
    if (tid < Nc) {
        const float4* Qr = (const float4*)(Q + base + (size_t)tid * Dc);
#pragma unroll
        for (int j = 0; j < 16; j++) q4[j] = Qr[j];
    }

    // ---- phase 1: stage K AND V into SMEM via cp.async; init rank ----
    {
        uint32_t sb = (uint32_t)__cvta_generic_to_shared(sm);
        const float4* K4 = (const float4*)(K + base);
        const float4* V4 = (const float4*)(V + base);
        for (int i = tid; i < Nc * Dc / 4; i += NT) {
            int n = i >> 4, d4 = i & 15;
            uint32_t off = (uint32_t)(n * KVS + d4 * 4) * 4u;
            cp_async16(sb + (OFF_K * 4u) + off, K4 + i);
            cp_async16(sb + (OFF_V * 4u) + off, V4 + i);
        }
        asm volatile("cp.async.commit_group;\n");
        for (int i = tid; i < Nc; i += NT) sRank[i] = -1;
        asm volatile("cp.async.wait_group 0;\n" ::: "memory");
    }
    __syncthreads();

    // ---- phase 2: sparsity measure M[n] = max_u(qk) - mean_u(qk) ----
    if (tid < Nc) {
        float mx = -INFINITY, sum = 0.f;
        const int* idxp = g_idx + tid * Uc;
#pragma unroll 2
        for (int u = 0; u < Uc; u += 2) {
            int kn0 = idxp[u], kn1 = idxp[u + 1];
            const float4* kr0 = (const float4*)&sK[kn0 * KVS];
            const float4* kr1 = (const float4*)&sK[kn1 * KVS];
            float a0 = 0.f, a1 = 0.f, a2 = 0.f, a3 = 0.f;
            float b0 = 0.f, b1 = 0.f, b2 = 0.f, b3 = 0.f;
#pragma unroll
            for (int j = 0; j < 16; j += 4) {
                a0 += dot4(q4[j],     kr0[j]);
                a1 += dot4(q4[j + 1], kr0[j + 1]);
                a2 += dot4(q4[j + 2], kr0[j + 2]);
                a3 += dot4(q4[j + 3], kr0[j + 3]);
                b0 += dot4(q4[j],     kr1[j]);
                b1 += dot4(q4[j + 1], kr1[j + 1]);
                b2 += dot4(q4[j + 2], kr1[j + 2]);
                b3 += dot4(q4[j + 3], kr1[j + 3]);
            }
            float accA = (a0 + a1) + (a2 + a3);
            float accB = (b0 + b1) + (b2 + b3);
            mx = fmaxf(mx, fmaxf(accA, accB));
            sum += accA + accB;
        }
        sM[tid] = mx - sum * (1.0f / Uc);
    }
    __syncthreads();

    // ---- phase 3: top-30 via parallel rank counting (ties -> lowest index) ----
    if (tid < Nc) {
        float mi = sM[tid];
        int rank = 0;
        for (int j = 0; j < Nc; j++) {
            float mj = sM[j];   // broadcast read
            rank += (mj > mi) || (mj == mi && j < tid) ? 1 : 0;
        }
        if (rank < Uc) { sRank[tid] = rank; sSel[rank] = tid; }
    }
    __syncthreads();

    // ---- phase 4: gather selected queries + column-mean partials of V ----
    for (int i = tid; i < Uc * Dc; i += NT) {
        int u = i >> 6, d = i & 63;
        sQ[u * Dc + d] = Q[base + (size_t)sSel[u] * Dc + d];
    }
    {   // warp w sums rows [22w, 22w+22) of V into sRed[w*64 + d]
        int n0 = warp * 22, n1 = min(Nc, n0 + 22);
        float m0 = 0.f, m1 = 0.f;
        for (int n = n0; n < n1; n++) {
            m0 += sV[n * KVS + lane];
            m1 += sV[n * KVS + lane + 32];
        }
        sRed[warp * 64 + lane]      = m0;
        sRed[warp * 64 + lane + 32] = m1;
    }
    __syncthreads();

    // ---- phase 5+8 fused (barrier-free per warp): scores -> softmax -> GEMV ----
    // warps 0-1 additionally combine the mean (reads sRed, pre-barrier data)
    if (tid < Dc) {
        float s = 0.f;
#pragma unroll
        for (int k = 0; k < NW; k++) s += sRed[k * 64 + tid];
        sMean[tid] = s * (1.0f / Nc);
    }

    {
        const int u0 = warp, u1 = warp + NW;
        const int half = lane >> 4;         // 0 or 1
        const int lsub = lane & 15;
        const int d0 = half << 5;           // 0 or 32

        float4 qa[8], qb[8];
        const float4* qa4 = (const float4*)&sQ[u0 * Dc + d0];
        const float4* qb4 = (const float4*)&sQ[u1 * Dc + d0];
#pragma unroll
        for (int j = 0; j < 8; j++) { qa[j] = qa4[j]; qb[j] = qb4[j]; }

        // --- scores: lane pairs (l, l+16) split d; each K row read once/warp ---
        float e0r[NSTEP], e1r[NSTEP];
        float lmax0 = -INFINITY, lmax1 = -INFINITY;
#pragma unroll
        for (int t = 0; t < NSTEP; t++) {
            int bn  = t * 32;
            int alo = min(bn + lsub,      Nc - 1) * KVS + d0;
            int ahi = min(bn + 16 + lsub, Nc - 1) * KVS + d0;
            const float4* klo = (const float4*)&sK[alo];
            const float4* khi = (const float4*)&sK[ahi];
            float p00 = 0.f, p01 = 0.f, p10 = 0.f, p11 = 0.f;
#pragma unroll
            for (int j = 0; j < 8; j++) {
                float4 kl = klo[j], kh = khi[j];
                p00 += dot4(qa[j], kl);
                p01 += dot4(qb[j], kl);
                p10 += dot4(qa[j], kh);
                p11 += dot4(qb[j], kh);
            }
            p00 += __shfl_xor_sync(0xffffffffu, p00, 16);
            p01 += __shfl_xor_sync(0xffffffffu, p01, 16);
            p10 += __shfl_xor_sync(0xffffffffu, p10, 16);
            p11 += __shfl_xor_sync(0xffffffffu, p11, 16);
            int n = bn + lane;
            float s0 = (half ? p10 : p00) * 0.125f;
            float s1 = (half ? p11 : p01) * 0.125f;
            bool ok = (n < Nc);
            e0r[t] = s0; e1r[t] = s1;
            lmax0 = fmaxf(lmax0, ok ? s0 : -INFINITY);
            lmax1 = fmaxf(lmax1, ok ? s1 : -INFINITY);
        }
#pragma unroll
        for (int o = 16; o > 0; o >>= 1) {
            lmax0 = fmaxf(lmax0, __shfl_xor_sync(0xffffffffu, lmax0, o));
            lmax1 = fmaxf(lmax1, __shfl_xor_sync(0xffffffffu, lmax1, o));
        }
        // --- softmax numerators in registers (e=0 beyond Nc) ---
        float lsum0 = 0.f, lsum1 = 0.f;
#pragma unroll
        for (int t = 0; t < NSTEP; t++) {
            bool ok = (t * 32 + lane) < Nc;
            float e0 = ok ? __expf(e0r[t] - lmax0) : 0.f;
            float e1 = ok ? __expf(e1r[t] - lmax1) : 0.f;
            e0r[t] = e0; e1r[t] = e1;
            lsum0 += e0; lsum1 += e1;
        }
#pragma unroll
        for (int o = 16; o > 0; o >>= 1) {
            lsum0 += __shfl_xor_sync(0xffffffffu, lsum0, o);
            lsum1 += __shfl_xor_sync(0xffffffffu, lsum1, o);
        }
        float inv0 = 1.0f / lsum0;
        float inv1 = 1.0f / lsum1;

        // --- GEMV: broadcast e via shfl, V rows conflict-free ---
        float a00 = 0.f, a01 = 0.f, a10 = 0.f, a11 = 0.f;
#pragma unroll
        for (int t = 0; t < NSTEP; t++) {
            const int cnt = (t == NSTEP - 1) ? (Nc - (NSTEP - 1) * 32) : 32;
            float e0v = e0r[t], e1v = e1r[t];
            const float* vb = &sV[t * 32 * KVS];
#pragma unroll 4
            for (int l = 0; l < cnt; l++) {
                float ee0 = __shfl_sync(0xffffffffu, e0v, l);
                float ee1 = __shfl_sync(0xffffffffu, e1v, l);
                float v0 = vb[l * KVS + lane];
                float v1 = vb[l * KVS + lane + 32];
                a00 += ee0 * v0; a01 += ee0 * v1;
                a10 += ee1 * v0; a11 += ee1 * v1;
            }
        }
        sUpd[u0 * Dc + lane]      = a00 * inv0;
        sUpd[u0 * Dc + lane + 32] = a01 * inv0;
        sUpd[u1 * Dc + lane]      = a10 * inv1;
        sUpd[u1 * Dc + lane + 32] = a11 * inv1;
    }
    __syncthreads();

    // ---- phase 9: write output (selected -> attention, else column mean) ----
    {
        const int b = g / (Hc * Tc);
        const int h = (g / Tc) % Hc;
        const int t = g % Tc;
        for (int i = tid; i < Nc * Dc / 4; i += NT) {
            int n = i >> 4, d4 = (i & 15) * 4;
            int r = sRank[n];
            float4 v = (r >= 0) ? *(float4*)&sUpd[r * Dc + d4]
                                : *(float4*)&sMean[d4];
            size_t o = ((size_t)(b * Nc + n) * Tc + t) * (size_t)(Hc * Dc)
                     + h * Dc + d4;
            *(float4*)&out[o] = v;
        }
    }
}

// ---------------- launch ----------------
extern "C" void kernel_launch(void* const* d_in, const int* in_sizes, int n_in,
                              void* d_out, int out_size) {
    const float* Q = (const float*)d_in[0];
    const float* K = (const float*)d_in[1];
    const float* V = (const float*)d_in[2];
    float* out = (float*)d_out;

    cudaFuncSetAttribute(probsparse_kernel,
                         cudaFuncAttributeMaxDynamicSharedMemorySize, SMEM_BYTES);

    idx_kernel<<<(Nc * Uc + 255) / 256, 256>>>();
    probsparse_kernel<<<Gc, NT, SMEM_BYTES>>>(Q, K, V, out);
}